// round 7
// baseline (speedup 1.0000x reference)
#include <cuda_runtime.h>

#define BB 4096
#define NN 8192
#define DD 512
#define RR 4
#define NBLK (NN / 4)   // 2048 blocks, 4 rows (warps) per block

__device__ float g_partial[NBLK];
__device__ unsigned int g_ticket;   // zero-initialized at module load; reset by last block

__device__ __forceinline__ const float4* row_ptr4(const float* zi, const float* zj, int r) {
    const float* p = (r < BB) ? (zi + (size_t)r * DD) : (zj + (size_t)(r - BB) * DD);
    return reinterpret_cast<const float4*>(p);
}

// One warp per row: fused norms + 5 dots + NLL. Block-level partial sum,
// last-finishing block does the deterministic final reduction.
__global__ void __launch_bounds__(128) fused_kernel(const float* __restrict__ zi,
                                                    const float* __restrict__ zj,
                                                    const int* __restrict__ neg_idx,
                                                    float* __restrict__ out) {
    __shared__ float s_nll[4];
    __shared__ bool  s_last;

    int warp = threadIdx.x >> 5;
    int lane = threadIdx.x & 31;
    int row  = blockIdx.x * 4 + warp;

    // ---- per-row work ----
    const float4* pi = row_ptr4(zi, zj, row);
    float4 x[4];
#pragma unroll
    for (int k = 0; k < 4; k++) x[k] = pi[lane + 32 * k];

    int4 nv = *reinterpret_cast<const int4*>(neg_idx + row * RR);
    int part[5];
    part[0] = (row + BB) & (NN - 1);
    part[1] = nv.x + (nv.x >= row ? 1 : 0);
    part[2] = nv.y + (nv.y >= row ? 1 : 0);
    part[3] = nv.z + (nv.z >= row ? 1 : 0);
    part[4] = nv.w + (nv.w >= row ? 1 : 0);

    // Front-load all partner data: 20 independent LDG.128 in flight
    float4 y[5][4];
#pragma unroll
    for (int p = 0; p < 5; p++) {
        const float4* pj = row_ptr4(zi, zj, part[p]);
#pragma unroll
        for (int k = 0; k < 4; k++) y[p][k] = pj[lane + 32 * k];
    }

    float x2 = 0.0f;
#pragma unroll
    for (int k = 0; k < 4; k++)
        x2 += x[k].x * x[k].x + x[k].y * x[k].y + x[k].z * x[k].z + x[k].w * x[k].w;

    float dot[5], y2[5];
#pragma unroll
    for (int p = 0; p < 5; p++) {
        float d = 0.0f, n = 0.0f;
#pragma unroll
        for (int k = 0; k < 4; k++) {
            float4 a = x[k], b = y[p][k];
            d += a.x * b.x + a.y * b.y + a.z * b.z + a.w * b.w;
            n += b.x * b.x + b.y * b.y + b.z * b.z + b.w * b.w;
        }
        dot[p] = d;
        y2[p]  = n;
    }

#pragma unroll
    for (int o = 16; o; o >>= 1) {
        x2 += __shfl_xor_sync(0xFFFFFFFFu, x2, o);
#pragma unroll
        for (int p = 0; p < 5; p++) {
            dot[p] += __shfl_xor_sync(0xFFFFFFFFu, dot[p], o);
            y2[p]  += __shfl_xor_sync(0xFFFFFFFFu, y2[p], o);
        }
    }

    if (lane == 0) {
        const float invT = 1.0f / (0.5f + 1e-8f);
        float rnx = 1.0f / fmaxf(sqrtf(x2), 1e-8f);
        float l[5];
#pragma unroll
        for (int p = 0; p < 5; p++) {
            float rny = 1.0f / fmaxf(sqrtf(y2[p]), 1e-8f);
            l[p] = dot[p] * rnx * rny * invT;
        }
        float m = l[0];
#pragma unroll
        for (int p = 1; p < 5; p++) m = fmaxf(m, l[p]);
        float se = 0.0f;
#pragma unroll
        for (int p = 0; p < 5; p++) se += expf(l[p] - m);
        s_nll[warp] = m + logf(se) - l[0];
    }
    __syncthreads();

    // ---- block partial (fixed order) + last-block final reduce ----
    if (threadIdx.x == 0) {
        float partial = s_nll[0] + s_nll[1] + s_nll[2] + s_nll[3];
        g_partial[blockIdx.x] = partial;
        __threadfence();
        unsigned int t = atomicAdd(&g_ticket, 1u);
        s_last = (t == (unsigned int)(NBLK - 1));
    }
    __syncthreads();

    if (s_last) {
        // 128 threads, each sums 16 partials in fixed stride order
        float s = 0.0f;
#pragma unroll
        for (int k = 0; k < NBLK / 128; k++) {
            float v;
            asm volatile("ld.global.cg.f32 %0, [%1];"
                         : "=f"(v)
                         : "l"(&g_partial[threadIdx.x + k * 128]));
            s += v;
        }
#pragma unroll
        for (int o = 16; o; o >>= 1) s += __shfl_xor_sync(0xFFFFFFFFu, s, o);
        if (lane == 0) s_nll[warp] = s;
        __syncthreads();
        if (threadIdx.x == 0) {
            float tot = s_nll[0] + s_nll[1] + s_nll[2] + s_nll[3];
            out[0] = tot * (1.0f / (float)NN);
            g_ticket = 0u;   // reset for next graph replay
        }
    }
}

extern "C" void kernel_launch(void* const* d_in, const int* in_sizes, int n_in,
                              void* d_out, int out_size) {
    const float* zi      = (const float*)d_in[0];
    const float* zj      = (const float*)d_in[1];
    const int*   neg_idx = (const int*)d_in[2];
    float* out = (float*)d_out;

    fused_kernel<<<NBLK, 128>>>(zi, zj, neg_idx, out);
}